// round 9
// baseline (speedup 1.0000x reference)
#include <cuda_runtime.h>
#include <math.h>

#define D_FEAT 8192
#define T_RES  2048
#define ORDER  16
#define DTAU   0.08
#define REG    0.0001f
#define EPS_C  1e-15f

#define ROW_BLOCKS 1024  // 2 rows per block, 4 warps per row
#define COL_BLOCKS 1024  // 8 columns per block
#define NW 256

// ---------------- device scratch (no allocations allowed) ----------------
__device__ float g_s[ORDER * T_RES];          // s_j = R q_j
__device__ float g_sf[T_RES];                 // R f
__device__ float g_Q[ORDER * D_FEAT];         // Lanczos basis
__device__ float g_wf[D_FEAT];                // current unnormalized basis vector
__device__ float g_nrm2_part[COL_BLOCKS];     // ||wf||^2 partials
__device__ float g_cpart[ROW_BLOCKS * ORDER]; // per-row-block partials of c_k
__device__ float g_b[ORDER + 1];              // g_b[0]=||F||, g_b[j]=beta[j-1]
__device__ float g_alpha[ORDER];

__device__ __forceinline__ void fma4(float4& a, const float4 r, const float4 v) {
    a.x = fmaf(r.x, v.x, a.x); a.y = fmaf(r.y, v.y, a.y);
    a.z = fmaf(r.z, v.z, a.z); a.w = fmaf(r.w, v.w, a.w);
}

// ============ prologue row: sf = R f (2 rows/block, 4 warps/row) ============
__global__ void k_row_f(const float* __restrict__ R, const float* __restrict__ f) {
    __shared__ float shp[8];
    int tx = threadIdx.x, lane = tx & 31, w = tx >> 5;
    int row = blockIdx.x * 2 + (w >> 2);
    int q = w & 3;                       // quarter of the row
    const float4* R4 = (const float4*)R;
    const float4* f4 = (const float4*)f;
    size_t rbase = (size_t)row * (D_FEAT / 4) + q * 512;
    int fbase = q * 512;
    float4 a0 = make_float4(0.f,0.f,0.f,0.f), a1 = a0, a2 = a0, a3 = a0;
    #pragma unroll
    for (int it = 0; it < 16; it += 4) {
        fma4(a0, R4[rbase + (it+0)*32 + lane], f4[fbase + (it+0)*32 + lane]);
        fma4(a1, R4[rbase + (it+1)*32 + lane], f4[fbase + (it+1)*32 + lane]);
        fma4(a2, R4[rbase + (it+2)*32 + lane], f4[fbase + (it+2)*32 + lane]);
        fma4(a3, R4[rbase + (it+3)*32 + lane], f4[fbase + (it+3)*32 + lane]);
    }
    a0.x += a1.x; a0.y += a1.y; a0.z += a1.z; a0.w += a1.w;
    a2.x += a3.x; a2.y += a3.y; a2.z += a3.z; a2.w += a3.w;
    float acc = (a0.x + a0.y) + (a0.z + a0.w) + (a2.x + a2.y) + (a2.z + a2.w);
    #pragma unroll
    for (int o = 16; o; o >>= 1) acc += __shfl_xor_sync(0xffffffffu, acc, o);
    if (lane == 0) shp[w] = acc;
    __syncthreads();
    if (w == 0 && lane < 8) {
        float p = shp[lane];
        p += __shfl_xor_sync(0xffu, p, 1);
        p += __shfl_xor_sync(0xffu, p, 2);
        if (lane == 0) g_sf[blockIdx.x * 2]     = p;
        if (lane == 4) g_sf[blockIdx.x * 2 + 1] = p;
    }
}

// ====== prologue col: F = R^T sf + E f ; wf = F ; ||F||^2 partials ======
__global__ void k_prologue_col(const float* __restrict__ R, const float* __restrict__ f) {
    __shared__ float s_sm[T_RES];
    __shared__ float4 sh[NW];
    __shared__ float sh_r1[8], sh_r2[8];
    __shared__ float shE;
    int tx = threadIdx.x, lane = tx & 31, w = tx >> 5;
    const float4* f4 = (const float4*)f;

    // stage sf; per-block redundant ||sf||^2 and ||f||^2 (L2-hot, deterministic)
    float ssf = 0.f;
    for (int i = tx; i < T_RES / 4; i += NW) {
        float4 v = ((const float4*)g_sf)[i];
        ((float4*)s_sm)[i] = v;
        ssf = fmaf(v.x, v.x, fmaf(v.y, v.y, fmaf(v.z, v.z, fmaf(v.w, v.w, ssf))));
    }
    float ff = 0.f;
    for (int i = tx; i < D_FEAT / 4; i += NW) {
        float4 v = f4[i];
        ff = fmaf(v.x, v.x, fmaf(v.y, v.y, fmaf(v.z, v.z, fmaf(v.w, v.w, ff))));
    }
    #pragma unroll
    for (int o = 16; o; o >>= 1) {
        ssf += __shfl_xor_sync(0xffffffffu, ssf, o);
        ff  += __shfl_xor_sync(0xffffffffu, ff, o);
    }
    if (lane == 0) { sh_r1[w] = ssf; sh_r2[w] = ff; }
    __syncthreads();
    if (tx == 0) {
        float a = 0.f, b = 0.f;
        #pragma unroll
        for (int i = 0; i < 8; i++) { a += sh_r1[i]; b += sh_r2[i]; }
        shE = -a / (b + EPS_C);
    }
    __syncthreads();

    // u[col] = sum_t R[t][col] * sf[t]  (8 cols per block)
    int g = tx & 1, s = tx >> 1;
    const float4* R4 = (const float4*)R;
    size_t cbase = (size_t)blockIdx.x * 2 + g;
    float4 a0 = make_float4(0.f,0.f,0.f,0.f), a1 = a0, a2 = a0, a3 = a0;
    #pragma unroll
    for (int it = 0; it < 16; it += 4) {
        int t0 = (it+0)*128 + s, t1 = (it+1)*128 + s, t2 = (it+2)*128 + s, t3 = (it+3)*128 + s;
        float4 r0 = R4[(size_t)t0 * (D_FEAT/4) + cbase];
        float4 r1 = R4[(size_t)t1 * (D_FEAT/4) + cbase];
        float4 r2 = R4[(size_t)t2 * (D_FEAT/4) + cbase];
        float4 r3 = R4[(size_t)t3 * (D_FEAT/4) + cbase];
        float s0 = s_sm[t0], s1 = s_sm[t1], s2 = s_sm[t2], s3 = s_sm[t3];
        a0.x = fmaf(r0.x, s0, a0.x); a0.y = fmaf(r0.y, s0, a0.y); a0.z = fmaf(r0.z, s0, a0.z); a0.w = fmaf(r0.w, s0, a0.w);
        a1.x = fmaf(r1.x, s1, a1.x); a1.y = fmaf(r1.y, s1, a1.y); a1.z = fmaf(r1.z, s1, a1.z); a1.w = fmaf(r1.w, s1, a1.w);
        a2.x = fmaf(r2.x, s2, a2.x); a2.y = fmaf(r2.y, s2, a2.y); a2.z = fmaf(r2.z, s2, a2.z); a2.w = fmaf(r2.w, s2, a2.w);
        a3.x = fmaf(r3.x, s3, a3.x); a3.y = fmaf(r3.y, s3, a3.y); a3.z = fmaf(r3.z, s3, a3.z); a3.w = fmaf(r3.w, s3, a3.w);
    }
    a0.x += a1.x; a0.y += a1.y; a0.z += a1.z; a0.w += a1.w;
    a2.x += a3.x; a2.y += a3.y; a2.z += a3.z; a2.w += a3.w;
    a0.x += a2.x; a0.y += a2.y; a0.z += a2.z; a0.w += a2.w;
    sh[tx] = a0;
    #pragma unroll
    for (int off = 128; off >= 2; off >>= 1) {
        __syncthreads();
        if (tx < off) {
            float4 a = sh[tx], b2 = sh[tx + off];
            a.x += b2.x; a.y += b2.y; a.z += b2.z; a.w += b2.w;
            sh[tx] = a;
        }
    }
    __syncthreads();

    if (tx < 8) {
        float u = ((const float*)sh)[tx];
        int col = blockIdx.x * 8 + tx;
        float F = fmaf(shE, f[col], u);
        g_wf[col] = F;
        float nrm = F * F;
        nrm += __shfl_xor_sync(0xffu, nrm, 4);
        nrm += __shfl_xor_sync(0xffu, nrm, 2);
        nrm += __shfl_xor_sync(0xffu, nrm, 1);
        if (tx == 0) g_nrm2_part[blockIdx.x] = nrm;
    }
}

// == k_A: b=||wf||; s_j = R*(wf/b); c-partials (2 rows/block, 4 warps/row) ==
__global__ void k_A(const float* __restrict__ R, int j) {
    __shared__ float sh_r[8];
    __shared__ float sh_invb;
    __shared__ float shp[8];
    int tx = threadIdx.x, lane = tx & 31, w = tx >> 5;

    // reduce 1024 nrm2 partials
    float p = g_nrm2_part[tx] + g_nrm2_part[tx + 256]
            + g_nrm2_part[tx + 512] + g_nrm2_part[tx + 768];
    #pragma unroll
    for (int o = 16; o; o >>= 1) p += __shfl_xor_sync(0xffffffffu, p, o);
    if (lane == 0) sh_r[w] = p;
    __syncthreads();
    if (tx == 0) {
        float n = 0.f;
        #pragma unroll
        for (int i = 0; i < 8; i++) n += sh_r[i];
        float b = sqrtf(n);
        if (blockIdx.x == 0) g_b[j] = b;
        sh_invb = 1.0f / fmaxf(b, 1e-30f);
    }

    int r0 = blockIdx.x * 2;
    int row = r0 + (w >> 2);
    int q = w & 3;
    const float4* R4 = (const float4*)R;
    const float4* w4 = (const float4*)g_wf;
    size_t rbase = (size_t)row * (D_FEAT / 4) + q * 512;
    int fbase = q * 512;
    float4 a0 = make_float4(0.f,0.f,0.f,0.f), a1 = a0, a2 = a0, a3 = a0;
    #pragma unroll
    for (int it = 0; it < 16; it += 4) {
        fma4(a0, R4[rbase + (it+0)*32 + lane], w4[fbase + (it+0)*32 + lane]);
        fma4(a1, R4[rbase + (it+1)*32 + lane], w4[fbase + (it+1)*32 + lane]);
        fma4(a2, R4[rbase + (it+2)*32 + lane], w4[fbase + (it+2)*32 + lane]);
        fma4(a3, R4[rbase + (it+3)*32 + lane], w4[fbase + (it+3)*32 + lane]);
    }
    a0.x += a1.x; a0.y += a1.y; a0.z += a1.z; a0.w += a1.w;
    a2.x += a3.x; a2.y += a3.y; a2.z += a3.z; a2.w += a3.w;
    float acc = (a0.x + a0.y) + (a0.z + a0.w) + (a2.x + a2.y) + (a2.z + a2.w);
    #pragma unroll
    for (int o = 16; o; o >>= 1) acc += __shfl_xor_sync(0xffffffffu, acc, o);
    if (lane == 0) shp[w] = acc;
    __syncthreads();

    if (w == 0) {
        float d = (lane < 8) ? shp[lane] : 0.f;
        d += __shfl_xor_sync(0xffffffffu, d, 1);
        d += __shfl_xor_sync(0xffffffffu, d, 2);     // lanes0-3: row0 dot, 4-7: row1 dot
        float invb = sh_invb;
        float s0 = __shfl_sync(0xffffffffu, d, 0) * invb;
        float s1 = __shfl_sync(0xffffffffu, d, 4) * invb;
        if (lane == 0) {
            g_s[j * T_RES + r0]     = s0;
            g_s[j * T_RES + r0 + 1] = s1;
        }
        // c-partials: lane = ro*16 + k
        int k = lane & 15, ro = lane >> 4;
        float sjr = ro ? s1 : s0;
        float cp = 0.f;
        if (k <= j) {
            float skr = (k == j) ? sjr : g_s[k * T_RES + r0 + ro];
            cp = skr * sjr;
        }
        cp += __shfl_down_sync(0xffffffffu, cp, 16);
        if (lane < 16) g_cpart[blockIdx.x * 16 + lane] = cp;
    }
}

// ===== k_B: reduce c; w = -R^T s_j + sum c_k Q[k]; Q[j]=wf/b; new wf =====
__global__ void k_B(const float* __restrict__ R, int j, int last) {
    __shared__ float s_sm[T_RES];
    __shared__ float4 sh[NW];
    __shared__ float sh_c[ORDER];
    int tx = threadIdx.x;
    float invb = 1.0f / fmaxf(g_b[j], 1e-30f);

    // reduce c-partials (1024 blocks x 16)
    {
        int k = tx >> 4, i = tx & 15;
        float c = 0.f;
        #pragma unroll 8
        for (int m = 0; m < ROW_BLOCKS / 16; m++)
            c += g_cpart[(m * 16 + i) * 16 + k];
        #pragma unroll
        for (int o = 8; o; o >>= 1) c += __shfl_xor_sync(0xffffffffu, c, o);
        if (i == 0) sh_c[k] = c;
    }
    const float4* sj4 = (const float4*)(g_s + (size_t)j * T_RES);
    for (int i = tx; i < T_RES / 4; i += NW) ((float4*)s_sm)[i] = sj4[i];
    __syncthreads();

    if (blockIdx.x == 0 && tx == 0) g_alpha[j] = -sh_c[j];

    if (last) {
        if (tx < 8) {
            int col = blockIdx.x * 8 + tx;
            g_Q[(size_t)j * D_FEAT + col] = g_wf[col] * invb;
        }
        return;
    }

    // u[col] = sum_t R[t][col] * s_j[t]  (8 cols per block)
    int g = tx & 1, s = tx >> 1;
    const float4* R4 = (const float4*)R;
    size_t cbase = (size_t)blockIdx.x * 2 + g;
    float4 a0 = make_float4(0.f,0.f,0.f,0.f), a1 = a0, a2 = a0, a3 = a0;
    #pragma unroll
    for (int it = 0; it < 16; it += 4) {
        int t0 = (it+0)*128 + s, t1 = (it+1)*128 + s, t2 = (it+2)*128 + s, t3 = (it+3)*128 + s;
        float4 r0 = R4[(size_t)t0 * (D_FEAT/4) + cbase];
        float4 r1 = R4[(size_t)t1 * (D_FEAT/4) + cbase];
        float4 r2 = R4[(size_t)t2 * (D_FEAT/4) + cbase];
        float4 r3 = R4[(size_t)t3 * (D_FEAT/4) + cbase];
        float s0 = s_sm[t0], s1 = s_sm[t1], s2 = s_sm[t2], s3 = s_sm[t3];
        a0.x = fmaf(r0.x, s0, a0.x); a0.y = fmaf(r0.y, s0, a0.y); a0.z = fmaf(r0.z, s0, a0.z); a0.w = fmaf(r0.w, s0, a0.w);
        a1.x = fmaf(r1.x, s1, a1.x); a1.y = fmaf(r1.y, s1, a1.y); a1.z = fmaf(r1.z, s1, a1.z); a1.w = fmaf(r1.w, s1, a1.w);
        a2.x = fmaf(r2.x, s2, a2.x); a2.y = fmaf(r2.y, s2, a2.y); a2.z = fmaf(r2.z, s2, a2.z); a2.w = fmaf(r2.w, s2, a2.w);
        a3.x = fmaf(r3.x, s3, a3.x); a3.y = fmaf(r3.y, s3, a3.y); a3.z = fmaf(r3.z, s3, a3.z); a3.w = fmaf(r3.w, s3, a3.w);
    }
    a0.x += a1.x; a0.y += a1.y; a0.z += a1.z; a0.w += a1.w;
    a2.x += a3.x; a2.y += a3.y; a2.z += a3.z; a2.w += a3.w;
    a0.x += a2.x; a0.y += a2.y; a0.z += a2.z; a0.w += a2.w;
    sh[tx] = a0;
    #pragma unroll
    for (int off = 128; off >= 2; off >>= 1) {
        __syncthreads();
        if (tx < off) {
            float4 a = sh[tx], b2 = sh[tx + off];
            a.x += b2.x; a.y += b2.y; a.z += b2.z; a.w += b2.w;
            sh[tx] = a;
        }
    }
    __syncthreads();

    if (tx < 8) {
        float u = ((const float*)sh)[tx];
        int col = blockIdx.x * 8 + tx;
        float qv = g_wf[col] * invb;
        g_Q[(size_t)j * D_FEAT + col] = qv;
        float wv = -u;
        for (int k = 0; k < j; k++)
            wv = fmaf(sh_c[k], g_Q[(size_t)k * D_FEAT + col], wv);
        wv = fmaf(sh_c[j], qv, wv);
        g_wf[col] = wv;
        float nrm = wv * wv;
        nrm += __shfl_xor_sync(0xffu, nrm, 4);
        nrm += __shfl_xor_sync(0xffu, nrm, 2);
        nrm += __shfl_xor_sync(0xffu, nrm, 1);
        if (tx == 0) g_nrm2_part[blockIdx.x] = nrm;
    }
}

// == k_final: expm (inlined, warp0) + dtheta[p] = D[p].dir / (||D[p]||^2+REG) ==
__global__ void k_final(const float* __restrict__ Dm, float* __restrict__ out) {
    __shared__ float sh_a[8], sh_d[8];
    __shared__ float coeffs[ORDER];
    int p = blockIdx.x;
    int tx = threadIdx.x, lane = tx & 31, w = tx >> 5;

    if (w == 0) {  // exp(-T*DTAU) e0 via lane-parallel double Taylor
        double a = 0.0, bl = 0.0, bu = 0.0;
        if (lane < ORDER) a = (double)g_alpha[lane];
        if (lane >= 1 && lane < ORDER) bl = (double)g_b[lane];
        if (lane < ORDER - 1) bu = (double)g_b[lane + 1];
        double v = (lane == 0) ? 1.0 : 0.0, y = v;
        for (int k = 1; k <= 40; k++) {
            double vp = __shfl_up_sync(0xffffffffu, v, 1);
            double vn = __shfl_down_sync(0xffffffffu, v, 1);
            double t = a * v + bl * vp + bu * vn;
            v = t * (-DTAU / (double)k);
            y += v;
        }
        if (lane < ORDER) coeffs[lane] = (float)((double)g_b[0] * y);
    }
    __syncthreads();

    float cf[ORDER];
    #pragma unroll
    for (int l = 0; l < ORDER; l++) cf[l] = coeffs[l];
    const float* Dp = Dm + (size_t)p * D_FEAT;
    float acc = 0.f, den = 0.f;
    for (int d = tx; d < D_FEAT; d += NW) {
        float dir = 0.f;
        #pragma unroll
        for (int l = 0; l < ORDER; l++) dir = fmaf(cf[l], g_Q[(size_t)l * D_FEAT + d], dir);
        float dv = Dp[d];
        acc = fmaf(dv, dir, acc);
        den = fmaf(dv, dv, den);
    }
    #pragma unroll
    for (int o = 16; o; o >>= 1) {
        acc += __shfl_xor_sync(0xffffffffu, acc, o);
        den += __shfl_xor_sync(0xffffffffu, den, o);
    }
    if (lane == 0) { sh_a[w] = acc; sh_d[w] = den; }
    __syncthreads();
    if (tx == 0) {
        float A = 0.f, Dd = 0.f;
        #pragma unroll
        for (int i = 0; i < 8; i++) { A += sh_a[i]; Dd += sh_d[i]; }
        out[p] = A / (Dd + REG);
    }
}

// --------------------------------- launcher ----------------------------------
extern "C" void kernel_launch(void* const* d_in, const int* in_sizes, int n_in,
                              void* d_out, int out_size) {
    (void)out_size;
    const float* f = nullptr;
    const float* R = nullptr;
    const float* Dm = nullptr;
    for (int i = 0; i < n_in; i++) {
        if (in_sizes[i] == D_FEAT)               f  = (const float*)d_in[i];
        else if (in_sizes[i] == T_RES * D_FEAT)  R  = (const float*)d_in[i];
        else if (in_sizes[i] == ORDER * D_FEAT)  Dm = (const float*)d_in[i];
    }

    k_row_f<<<ROW_BLOCKS, NW>>>(R, f);
    k_prologue_col<<<COL_BLOCKS, NW>>>(R, f);
    for (int j = 0; j < ORDER; j++) {
        k_A<<<ROW_BLOCKS, NW>>>(R, j);
        k_B<<<COL_BLOCKS, NW>>>(R, j, (j == ORDER - 1) ? 1 : 0);
    }
    k_final<<<ORDER, NW>>>(Dm, (float*)d_out);
}

// round 10
// speedup vs baseline: 1.6091x; 1.6091x over previous
#include <cuda_runtime.h>
#include <math.h>

#define D_FEAT 8192
#define T_RES  2048
#define ORDER  16
#define DTAU   0.08
#define REG    0.0001f
#define EPS_C  1e-15f

#define ROW_BLOCKS 256   // row kernels: 8 warps/block, one row per warp
#define COL_BLOCKS 256   // col kernels: 32 columns per block, 512 threads
#define NW  256
#define NWC 512

// ---------------- device scratch (no allocations allowed) ----------------
__device__ float g_s[ORDER * T_RES];          // s_j = R q_j
__device__ float g_sf[T_RES];                 // R f
__device__ float g_Q[ORDER * D_FEAT];         // Lanczos basis
__device__ float g_wf[D_FEAT];                // current unnormalized basis vector
__device__ float g_nrm2_part[COL_BLOCKS];     // ||wf||^2 partials (per col-block)
__device__ float g_cpart[ROW_BLOCKS * ORDER]; // per-row-block partials of c_k
__device__ float g_b[ORDER + 1];              // g_b[0]=||F||, g_b[j]=beta[j-1]
__device__ float g_alpha[ORDER];

__device__ __forceinline__ void fma4(float4& a, const float4 r, const float4 v) {
    a.x = fmaf(r.x, v.x, a.x); a.y = fmaf(r.y, v.y, a.y);
    a.z = fmaf(r.z, v.z, a.z); a.w = fmaf(r.w, v.w, a.w);
}
__device__ __forceinline__ void fmas(float4& a, const float4 r, const float s) {
    a.x = fmaf(r.x, s, a.x); a.y = fmaf(r.y, s, a.y);
    a.z = fmaf(r.z, s, a.z); a.w = fmaf(r.w, s, a.w);
}

// ================= prologue row: sf = R f (warp per row) =================
__global__ void k_row_f(const float* __restrict__ R, const float* __restrict__ f) {
    int tx = threadIdx.x, lane = tx & 31, w = tx >> 5;
    int r = blockIdx.x * 8 + w;
    const float4* R4 = (const float4*)(R + (size_t)r * D_FEAT);
    const float4* f4 = (const float4*)f;
    float4 aA = make_float4(0.f,0.f,0.f,0.f), aB = aA;
    #pragma unroll 8
    for (int it = 0; it < 64; it += 2) {
        int i0 = it * 32 + lane, i1 = i0 + 32;
        fma4(aA, R4[i0], f4[i0]);
        fma4(aB, R4[i1], f4[i1]);
    }
    float acc = (aA.x + aA.y) + (aA.z + aA.w) + (aB.x + aB.y) + (aB.z + aB.w);
    #pragma unroll
    for (int o = 16; o; o >>= 1) acc += __shfl_xor_sync(0xffffffffu, acc, o);
    if (lane == 0) g_sf[r] = acc;
}

// ====== prologue col: F = R^T sf + E f ; wf = F ; ||F||^2 partials ======
// 32 cols/block, 512 threads: g=tx&7 -> full 128B line per 8 lanes.
__global__ void k_prologue_col(const float* __restrict__ R, const float* __restrict__ f) {
    __shared__ float s_sm[T_RES];
    __shared__ float4 sh[NWC];
    __shared__ float sh_r1[16], sh_r2[16];
    __shared__ float shE;
    int tx = threadIdx.x, lane = tx & 31, w = tx >> 5;
    const float4* f4 = (const float4*)f;

    // stage sf; per-block redundant ||sf||^2 and ||f||^2 (L2-hot, deterministic)
    float ssf = 0.f;
    for (int i = tx; i < T_RES / 4; i += NWC) {
        float4 v = ((const float4*)g_sf)[i];
        ((float4*)s_sm)[i] = v;
        ssf = fmaf(v.x, v.x, fmaf(v.y, v.y, fmaf(v.z, v.z, fmaf(v.w, v.w, ssf))));
    }
    float ff = 0.f;
    for (int i = tx; i < D_FEAT / 4; i += NWC) {
        float4 v = f4[i];
        ff = fmaf(v.x, v.x, fmaf(v.y, v.y, fmaf(v.z, v.z, fmaf(v.w, v.w, ff))));
    }
    #pragma unroll
    for (int o = 16; o; o >>= 1) {
        ssf += __shfl_xor_sync(0xffffffffu, ssf, o);
        ff  += __shfl_xor_sync(0xffffffffu, ff, o);
    }
    if (lane == 0) { sh_r1[w] = ssf; sh_r2[w] = ff; }
    __syncthreads();
    if (tx == 0) {
        float a = 0.f, b = 0.f;
        #pragma unroll
        for (int i = 0; i < 16; i++) { a += sh_r1[i]; b += sh_r2[i]; }
        shE = -a / (b + EPS_C);
    }
    __syncthreads();

    // u[col] = sum_t R[t][col]*sf[t]
    int g = tx & 7, s = tx >> 3;          // s in [0,64)
    const float4* R4 = (const float4*)R;
    size_t cbase = (size_t)blockIdx.x * 8 + g;
    float4 a0 = make_float4(0.f,0.f,0.f,0.f), a1 = a0, a2 = a0, a3 = a0;
    #pragma unroll
    for (int it = 0; it < 32; it += 4) {
        int t0 = (it+0)*64 + s, t1 = (it+1)*64 + s, t2 = (it+2)*64 + s, t3 = (it+3)*64 + s;
        fmas(a0, R4[(size_t)t0 * (D_FEAT/4) + cbase], s_sm[t0]);
        fmas(a1, R4[(size_t)t1 * (D_FEAT/4) + cbase], s_sm[t1]);
        fmas(a2, R4[(size_t)t2 * (D_FEAT/4) + cbase], s_sm[t2]);
        fmas(a3, R4[(size_t)t3 * (D_FEAT/4) + cbase], s_sm[t3]);
    }
    a0.x += a1.x; a0.y += a1.y; a0.z += a1.z; a0.w += a1.w;
    a2.x += a3.x; a2.y += a3.y; a2.z += a3.z; a2.w += a3.w;
    a0.x += a2.x; a0.y += a2.y; a0.z += a2.z; a0.w += a2.w;
    sh[tx] = a0;
    #pragma unroll
    for (int off = 256; off >= 8; off >>= 1) {
        __syncthreads();
        if (tx < off) {
            float4 a = sh[tx], b2 = sh[tx + off];
            a.x += b2.x; a.y += b2.y; a.z += b2.z; a.w += b2.w;
            sh[tx] = a;
        }
    }
    __syncthreads();

    if (tx < 32) {
        float u = ((const float*)sh)[tx];
        int col = blockIdx.x * 32 + tx;
        float F = fmaf(shE, f[col], u);
        g_wf[col] = F;
        float nrm = F * F;
        #pragma unroll
        for (int o = 16; o; o >>= 1) nrm += __shfl_xor_sync(0xffffffffu, nrm, o);
        if (tx == 0) g_nrm2_part[blockIdx.x] = nrm;
    }
}

// ===== k_A: b=||wf||; s_j = R*(wf/b); c-partials (warp per row) =====
__global__ void k_A(const float* __restrict__ R, int j) {
    __shared__ float sh_r[8];
    __shared__ float sh_invb;
    __shared__ float sh_cp[8][16];
    int tx = threadIdx.x, lane = tx & 31, w = tx >> 5;

    float p = g_nrm2_part[tx];            // COL_BLOCKS == NW
    #pragma unroll
    for (int o = 16; o; o >>= 1) p += __shfl_xor_sync(0xffffffffu, p, o);
    if (lane == 0) sh_r[w] = p;
    __syncthreads();
    if (tx == 0) {
        float n = 0.f;
        #pragma unroll
        for (int i = 0; i < 8; i++) n += sh_r[i];
        float b = sqrtf(n);
        if (blockIdx.x == 0) g_b[j] = b;
        sh_invb = 1.0f / fmaxf(b, 1e-30f);
    }
    __syncthreads();
    float invb = sh_invb;

    int r = blockIdx.x * 8 + w;
    const float4* R4 = (const float4*)(R + (size_t)r * D_FEAT);
    const float4* w4 = (const float4*)g_wf;
    float4 aA = make_float4(0.f,0.f,0.f,0.f), aB = aA;
    #pragma unroll 8
    for (int it = 0; it < 64; it += 2) {
        int i0 = it * 32 + lane, i1 = i0 + 32;
        fma4(aA, R4[i0], w4[i0]);
        fma4(aB, R4[i1], w4[i1]);
    }
    float acc = (aA.x + aA.y) + (aA.z + aA.w) + (aB.x + aB.y) + (aB.z + aB.w);
    #pragma unroll
    for (int o = 16; o; o >>= 1) acc += __shfl_xor_sync(0xffffffffu, acc, o);
    float sjr = acc * invb;               // all lanes hold s_j[r]
    if (lane == 0) g_s[j * T_RES + r] = sjr;

    float cp = 0.f;
    if (lane <= j) {                      // lane k contributes s_k[r]*s_j[r]
        float skr = (lane == j) ? sjr : g_s[lane * T_RES + r];
        cp = skr * sjr;
    }
    if (lane < 16) sh_cp[w][lane] = cp;
    __syncthreads();
    if (tx < 16) {
        float c = 0.f;
        #pragma unroll
        for (int i = 0; i < 8; i++) c += sh_cp[i][tx];
        g_cpart[blockIdx.x * 16 + tx] = c;
    }
}

// ===== k_B: reduce c; w = -R^T s_j + sum c_k Q[k]; Q[j]=wf/b; new wf =====
// 32 cols/block, 512 threads, full-line coalescing.
__global__ void k_B(const float* __restrict__ R, int j, int last) {
    __shared__ float s_sm[T_RES];
    __shared__ float4 sh[NWC];
    __shared__ float sh_c[ORDER];
    int tx = threadIdx.x;
    float invb = 1.0f / fmaxf(g_b[j], 1e-30f);

    if (tx < 256) {   // reduce c-partials (256 row-blocks x 16)
        int k = tx >> 4, i = tx & 15;
        float c = 0.f;
        #pragma unroll
        for (int m = 0; m < ROW_BLOCKS / 16; m++)
            c += g_cpart[(m * 16 + i) * 16 + k];
        #pragma unroll
        for (int o = 8; o; o >>= 1) c += __shfl_xor_sync(0xffffffffu, c, o);
        if (i == 0) sh_c[k] = c;
    }
    const float4* sj4 = (const float4*)(g_s + (size_t)j * T_RES);
    for (int i = tx; i < T_RES / 4; i += NWC) ((float4*)s_sm)[i] = sj4[i];
    __syncthreads();

    if (blockIdx.x == 0 && tx == 0) g_alpha[j] = -sh_c[j];

    if (last) {
        if (tx < 32) {
            int col = blockIdx.x * 32 + tx;
            g_Q[(size_t)j * D_FEAT + col] = g_wf[col] * invb;
        }
        return;
    }

    // u[col] = sum_t R[t][col] * s_j[t]
    int g = tx & 7, s = tx >> 3;          // s in [0,64)
    const float4* R4 = (const float4*)R;
    size_t cbase = (size_t)blockIdx.x * 8 + g;
    float4 a0 = make_float4(0.f,0.f,0.f,0.f), a1 = a0, a2 = a0, a3 = a0;
    #pragma unroll
    for (int it = 0; it < 32; it += 4) {
        int t0 = (it+0)*64 + s, t1 = (it+1)*64 + s, t2 = (it+2)*64 + s, t3 = (it+3)*64 + s;
        fmas(a0, R4[(size_t)t0 * (D_FEAT/4) + cbase], s_sm[t0]);
        fmas(a1, R4[(size_t)t1 * (D_FEAT/4) + cbase], s_sm[t1]);
        fmas(a2, R4[(size_t)t2 * (D_FEAT/4) + cbase], s_sm[t2]);
        fmas(a3, R4[(size_t)t3 * (D_FEAT/4) + cbase], s_sm[t3]);
    }
    a0.x += a1.x; a0.y += a1.y; a0.z += a1.z; a0.w += a1.w;
    a2.x += a3.x; a2.y += a3.y; a2.z += a3.z; a2.w += a3.w;
    a0.x += a2.x; a0.y += a2.y; a0.z += a2.z; a0.w += a2.w;
    sh[tx] = a0;
    #pragma unroll
    for (int off = 256; off >= 8; off >>= 1) {
        __syncthreads();
        if (tx < off) {
            float4 a = sh[tx], b2 = sh[tx + off];
            a.x += b2.x; a.y += b2.y; a.z += b2.z; a.w += b2.w;
            sh[tx] = a;
        }
    }
    __syncthreads();

    if (tx < 32) {
        float u = ((const float*)sh)[tx];
        int col = blockIdx.x * 32 + tx;
        float qv = g_wf[col] * invb;
        g_Q[(size_t)j * D_FEAT + col] = qv;
        float wv = -u;
        for (int k = 0; k < j; k++)
            wv = fmaf(sh_c[k], g_Q[(size_t)k * D_FEAT + col], wv);
        wv = fmaf(sh_c[j], qv, wv);
        g_wf[col] = wv;
        float nrm = wv * wv;
        #pragma unroll
        for (int o = 16; o; o >>= 1) nrm += __shfl_xor_sync(0xffffffffu, nrm, o);
        if (tx == 0) g_nrm2_part[blockIdx.x] = nrm;
    }
}

// == k_final: expm (inlined, warp0) + dtheta[p] = D[p].dir / (||D[p]||^2+REG) ==
__global__ void k_final(const float* __restrict__ Dm, float* __restrict__ out) {
    __shared__ float sh_a[8], sh_d[8];
    __shared__ float coeffs[ORDER];
    int p = blockIdx.x;
    int tx = threadIdx.x, lane = tx & 31, w = tx >> 5;

    if (w == 0) {  // exp(-T*DTAU) e0 via lane-parallel double Taylor
        double a = 0.0, bl = 0.0, bu = 0.0;
        if (lane < ORDER) a = (double)g_alpha[lane];
        if (lane >= 1 && lane < ORDER) bl = (double)g_b[lane];
        if (lane < ORDER - 1) bu = (double)g_b[lane + 1];
        double v = (lane == 0) ? 1.0 : 0.0, y = v;
        for (int k = 1; k <= 40; k++) {
            double vp = __shfl_up_sync(0xffffffffu, v, 1);
            double vn = __shfl_down_sync(0xffffffffu, v, 1);
            double t = a * v + bl * vp + bu * vn;
            v = t * (-DTAU / (double)k);
            y += v;
        }
        if (lane < ORDER) coeffs[lane] = (float)((double)g_b[0] * y);
    }
    __syncthreads();

    float cf[ORDER];
    #pragma unroll
    for (int l = 0; l < ORDER; l++) cf[l] = coeffs[l];
    const float* Dp = Dm + (size_t)p * D_FEAT;
    float acc = 0.f, den = 0.f;
    for (int d = tx; d < D_FEAT; d += NW) {
        float dir = 0.f;
        #pragma unroll
        for (int l = 0; l < ORDER; l++) dir = fmaf(cf[l], g_Q[(size_t)l * D_FEAT + d], dir);
        float dv = Dp[d];
        acc = fmaf(dv, dir, acc);
        den = fmaf(dv, dv, den);
    }
    #pragma unroll
    for (int o = 16; o; o >>= 1) {
        acc += __shfl_xor_sync(0xffffffffu, acc, o);
        den += __shfl_xor_sync(0xffffffffu, den, o);
    }
    if (lane == 0) { sh_a[w] = acc; sh_d[w] = den; }
    __syncthreads();
    if (tx == 0) {
        float A = 0.f, Dd = 0.f;
        #pragma unroll
        for (int i = 0; i < 8; i++) { A += sh_a[i]; Dd += sh_d[i]; }
        out[p] = A / (Dd + REG);
    }
}

// --------------------------------- launcher ----------------------------------
extern "C" void kernel_launch(void* const* d_in, const int* in_sizes, int n_in,
                              void* d_out, int out_size) {
    (void)out_size;
    const float* f = nullptr;
    const float* R = nullptr;
    const float* Dm = nullptr;
    for (int i = 0; i < n_in; i++) {
        if (in_sizes[i] == D_FEAT)               f  = (const float*)d_in[i];
        else if (in_sizes[i] == T_RES * D_FEAT)  R  = (const float*)d_in[i];
        else if (in_sizes[i] == ORDER * D_FEAT)  Dm = (const float*)d_in[i];
    }

    k_row_f<<<ROW_BLOCKS, NW>>>(R, f);
    k_prologue_col<<<COL_BLOCKS, NWC>>>(R, f);
    for (int j = 0; j < ORDER; j++) {
        k_A<<<ROW_BLOCKS, NW>>>(R, j);
        k_B<<<COL_BLOCKS, NWC>>>(R, j, (j == ORDER - 1) ? 1 : 0);
    }
    k_final<<<ORDER, NW>>>(Dm, (float*)d_out);
}